// round 1
// baseline (speedup 1.0000x reference)
#include <cuda_runtime.h>
#include <math.h>

#define NH    8
#define EDIM  32
#define WS    8
#define MO    12
#define NKEY  (MO*MO)      // 144
#define BATCH 16
#define CCH   256
#define HH    64
#define WW    64
#define PIX   (HH*WW)      // 4096
#define NWIN  8

// Scratch buffers (allocation-free rule: __device__ globals)
__device__ float g_Q[BATCH * NH * PIX * EDIM];    // (b, head, pixel, e)
__device__ float g_K[BATCH * NH * PIX * EDIM];
__device__ float g_V[BATCH * NH * PIX * EDIM];
__device__ float g_att[BATCH * PIX * CCH];        // (b, pixel, c)

// ---------------------------------------------------------------------------
// Kernel 1: QKV projection.  qkv[b,p,oc] = sum_c x[b,c,p] * W1[oc,c] + b1[oc]
// x layout (B,C,H,W) -> contiguous in pixel for fixed c (perfect for A-tile).
// Epilogue de-interleaves oc: type=oc%3 (Q/K/V), ch=oc/3, head=ch/32, e=ch%32.
// Tiling: BM=128 (pixels), BN=64 (out ch), BK=16, 256 threads, 8x4 microtile.
// ---------------------------------------------------------------------------
__global__ __launch_bounds__(256) void qkv_gemm(const float* __restrict__ x,
                                                const float* __restrict__ W1,
                                                const float* __restrict__ b1) {
    __shared__ float As[16][128];   // [k][m]
    __shared__ float Bs[16][65];    // [k][n] (padded)

    const int b  = blockIdx.z;
    const int p0 = blockIdx.x * 128;
    const int n0 = blockIdx.y * 64;
    const int tid = threadIdx.x;
    const int tr = tid >> 4;   // 0..15 -> m base tr*8
    const int tc = tid & 15;   // 0..15 -> n base tc*4

    const float* xb = x + (size_t)b * CCH * PIX;

    float acc[8][4];
#pragma unroll
    for (int i = 0; i < 8; i++)
#pragma unroll
        for (int j = 0; j < 4; j++) acc[i][j] = 0.f;

    for (int c0 = 0; c0 < CCH; c0 += 16) {
        // Load A tile: 16 x 128 = 512 float4, 2 per thread
#pragma unroll
        for (int t = 0; t < 2; t++) {
            int idx = tid + t * 256;          // 0..511
            int kk  = idx >> 5;               // 0..15
            int mm  = (idx & 31) * 4;         // 0..124
            float4 v = *(const float4*)(xb + (size_t)(c0 + kk) * PIX + p0 + mm);
            As[kk][mm + 0] = v.x; As[kk][mm + 1] = v.y;
            As[kk][mm + 2] = v.z; As[kk][mm + 3] = v.w;
        }
        // Load B tile: 64 x 16 from W1 (row-major, contiguous in c=k)
        {
            int nn = tid >> 2;                // 0..63
            int kk = (tid & 3) * 4;           // 0..12
            float4 v = *(const float4*)(W1 + (size_t)(n0 + nn) * CCH + c0 + kk);
            Bs[kk + 0][nn] = v.x; Bs[kk + 1][nn] = v.y;
            Bs[kk + 2][nn] = v.z; Bs[kk + 3][nn] = v.w;
        }
        __syncthreads();

#pragma unroll
        for (int kk = 0; kk < 16; kk++) {
            float a[8], bb[4];
#pragma unroll
            for (int i = 0; i < 8; i++) a[i] = As[kk][tr * 8 + i];
#pragma unroll
            for (int j = 0; j < 4; j++) bb[j] = Bs[kk][tc * 4 + j];
#pragma unroll
            for (int i = 0; i < 8; i++)
#pragma unroll
                for (int j = 0; j < 4; j++)
                    acc[i][j] = fmaf(a[i], bb[j], acc[i][j]);
        }
        __syncthreads();
    }

    // Epilogue: scatter into Q/K/V (b, head, pixel, e)
#pragma unroll
    for (int j = 0; j < 4; j++) {
        int oc   = n0 + tc * 4 + j;
        float bias = b1[oc];
        int type = oc % 3;
        int ch   = oc / 3;
        int head = ch >> 5;
        int e    = ch & 31;
        float* dst = (type == 0) ? g_Q : (type == 1) ? g_K : g_V;
        size_t base = ((size_t)(b * NH + head) * PIX) * EDIM + e;
#pragma unroll
        for (int i = 0; i < 8; i++) {
            int p = p0 + tr * 8 + i;
            dst[base + (size_t)p * EDIM] = acc[i][j] + bias;
        }
    }
}

// ---------------------------------------------------------------------------
// Kernel 2: windowed attention. One block per (b, head, window).
// 64 queries x 144 keys x E=32. Zero-padded OOB keys stay IN the softmax
// (score exactly 0), matching the reference's zero-pad semantics.
// ---------------------------------------------------------------------------
#define QS_STRIDE 33
#define KS_STRIDE 33
#define S_STRIDE  145
#define SMEM_FLOATS (64*QS_STRIDE + NKEY*KS_STRIDE + NKEY*KS_STRIDE + 64*S_STRIDE)

__global__ __launch_bounds__(128) void attn_kernel() {
    extern __shared__ float sm[];
    float* Qs = sm;                          // 64  x 33
    float* Ks = Qs + 64 * QS_STRIDE;         // 144 x 33
    float* Vs = Ks + NKEY * KS_STRIDE;       // 144 x 33
    float* S  = Vs + NKEY * KS_STRIDE;       // 64  x 145

    const int b    = blockIdx.z;
    const int head = blockIdx.y;
    const int wi   = blockIdx.x >> 3;
    const int wj   = blockIdx.x & 7;
    const int tid  = threadIdx.x;

    const size_t hb = (size_t)(b * NH + head) * PIX * EDIM;
    const float* Qg = g_Q + hb;
    const float* Kg = g_K + hb;
    const float* Vg = g_V + hb;

    // Load Q window (64 x 32)
    for (int idx = tid; idx < 64 * EDIM; idx += 128) {
        int q = idx >> 5, e = idx & 31;
        int r = wi * 8 + (q >> 3);
        int c = wj * 8 + (q & 7);
        Qs[q * QS_STRIDE + e] = Qg[(size_t)(r * WW + c) * EDIM + e];
    }
    // Load K/V halo (144 x 32), zero for OOB
    for (int idx = tid; idx < NKEY * EDIM; idx += 128) {
        int k = idx >> 5, e = idx & 31;
        int kr = k / MO, kc = k % MO;
        int r = wi * 8 - 2 + kr;
        int c = wj * 8 - 2 + kc;
        bool ok = (r >= 0) && (r < HH) && (c >= 0) && (c < WW);
        size_t off = (size_t)(r * WW + c) * EDIM + e;
        Ks[k * KS_STRIDE + e] = ok ? Kg[off] : 0.f;
        Vs[k * KS_STRIDE + e] = ok ? Vg[off] : 0.f;
    }
    __syncthreads();

    // Scores: thread tile = 8 queries x 9 keys
    {
        const int tq = tid >> 4;   // 0..7  -> q base tq*8
        const int tk = tid & 15;   // 0..15 -> k base tk*9
        float acc[8][9];
#pragma unroll
        for (int i = 0; i < 8; i++)
#pragma unroll
            for (int j = 0; j < 9; j++) acc[i][j] = 0.f;

        for (int e = 0; e < EDIM; e++) {
            float qv[8], kv[9];
#pragma unroll
            for (int i = 0; i < 8; i++) qv[i] = Qs[(tq * 8 + i) * QS_STRIDE + e];
#pragma unroll
            for (int j = 0; j < 9; j++) kv[j] = Ks[(tk * 9 + j) * KS_STRIDE + e];
#pragma unroll
            for (int i = 0; i < 8; i++)
#pragma unroll
                for (int j = 0; j < 9; j++)
                    acc[i][j] = fmaf(qv[i], kv[j], acc[i][j]);
        }
        const float scale = 0.17677669529663687f;  // 1/sqrt(32)
#pragma unroll
        for (int i = 0; i < 8; i++)
#pragma unroll
            for (int j = 0; j < 9; j++)
                S[(tq * 8 + i) * S_STRIDE + tk * 9 + j] = acc[i][j] * scale;
    }
    __syncthreads();

    // Softmax: one row per thread (tid < 64), over 144 keys
    if (tid < 64) {
        float* row = S + tid * S_STRIDE;
        float m = -1e30f;
        for (int k = 0; k < NKEY; k++) m = fmaxf(m, row[k]);
        float s = 0.f;
        for (int k = 0; k < NKEY; k++) {
            float ex = __expf(row[k] - m);
            row[k] = ex;
            s += ex;
        }
        float inv = 1.f / s;
        for (int k = 0; k < NKEY; k++) row[k] *= inv;
    }
    __syncthreads();

    // out = A @ V : 64 x 32, thread tile 4 queries x 4 e
    {
        const int tq = tid >> 3;  // 0..15 -> q base tq*4
        const int te = tid & 7;   // 0..7  -> e base te*4
        float acc[4][4];
#pragma unroll
        for (int i = 0; i < 4; i++)
#pragma unroll
            for (int j = 0; j < 4; j++) acc[i][j] = 0.f;

        for (int k = 0; k < NKEY; k++) {
            float a[4], v[4];
#pragma unroll
            for (int i = 0; i < 4; i++) a[i] = S[(tq * 4 + i) * S_STRIDE + k];
#pragma unroll
            for (int j = 0; j < 4; j++) v[j] = Vs[k * KS_STRIDE + te * 4 + j];
#pragma unroll
            for (int i = 0; i < 4; i++)
#pragma unroll
                for (int j = 0; j < 4; j++)
                    acc[i][j] = fmaf(a[i], v[j], acc[i][j]);
        }
        // Write to g_att[b][pixel][head*32 + e]
#pragma unroll
        for (int i = 0; i < 4; i++) {
            int q = tq * 4 + i;
            int r = wi * 8 + (q >> 3);
            int c = wj * 8 + (q & 7);
            float4 v4 = make_float4(acc[i][0], acc[i][1], acc[i][2], acc[i][3]);
            *(float4*)(g_att + ((size_t)b * PIX + r * WW + c) * CCH
                       + head * EDIM + te * 4) = v4;
        }
    }
}

// ---------------------------------------------------------------------------
// Kernel 3: output projection. y[b,n,p] = sum_c att[b,p,c]*W2[n,c] + b2[n]
// Output written directly in (B,C,H,W) layout (contiguous in p). Same tiling
// as qkv_gemm; A tile needs a transposed store (att is contiguous in c=k).
// ---------------------------------------------------------------------------
__global__ __launch_bounds__(256) void proj_gemm(const float* __restrict__ W2,
                                                 const float* __restrict__ b2,
                                                 float* __restrict__ y) {
    __shared__ float As[16][129];   // [k][m], padded (transposed scalar stores)
    __shared__ float Bs[16][65];    // [k][n]

    const int b  = blockIdx.z;
    const int p0 = blockIdx.x * 128;
    const int n0 = blockIdx.y * 64;
    const int tid = threadIdx.x;
    const int tr = tid >> 4;
    const int tc = tid & 15;

    const float* ab = g_att + (size_t)b * PIX * CCH;

    float acc[8][4];
#pragma unroll
    for (int i = 0; i < 8; i++)
#pragma unroll
        for (int j = 0; j < 4; j++) acc[i][j] = 0.f;

    for (int c0 = 0; c0 < CCH; c0 += 16) {
        // A tile: 128 pixels x 16 c. att contiguous in c -> float4 along k,
        // transposed store into As[k][m].
#pragma unroll
        for (int t = 0; t < 2; t++) {
            int idx = tid + t * 256;          // 0..511
            int mm  = idx >> 2;               // 0..127 (pixel)
            int kk  = (idx & 3) * 4;          // 0..12
            float4 v = *(const float4*)(ab + (size_t)(p0 + mm) * CCH + c0 + kk);
            As[kk + 0][mm] = v.x; As[kk + 1][mm] = v.y;
            As[kk + 2][mm] = v.z; As[kk + 3][mm] = v.w;
        }
        // B tile: 64 x 16 from W2
        {
            int nn = tid >> 2;
            int kk = (tid & 3) * 4;
            float4 v = *(const float4*)(W2 + (size_t)(n0 + nn) * CCH + c0 + kk);
            Bs[kk + 0][nn] = v.x; Bs[kk + 1][nn] = v.y;
            Bs[kk + 2][nn] = v.z; Bs[kk + 3][nn] = v.w;
        }
        __syncthreads();

#pragma unroll
        for (int kk = 0; kk < 16; kk++) {
            float a[8], bb[4];
#pragma unroll
            for (int i = 0; i < 8; i++) a[i] = As[kk][tr * 8 + i];
#pragma unroll
            for (int j = 0; j < 4; j++) bb[j] = Bs[kk][tc * 4 + j];
#pragma unroll
            for (int i = 0; i < 8; i++)
#pragma unroll
                for (int j = 0; j < 4; j++)
                    acc[i][j] = fmaf(a[i], bb[j], acc[i][j]);
        }
        __syncthreads();
    }

    // Output: y[b][n][p], contiguous in p -> float4 stores over i
#pragma unroll
    for (int j = 0; j < 4; j++) {
        int n = n0 + tc * 4 + j;
        float bias = b2[n];
        float* dst = y + ((size_t)(b * CCH + n)) * PIX + p0 + tr * 8;
        float4 v0 = make_float4(acc[0][j] + bias, acc[1][j] + bias,
                                acc[2][j] + bias, acc[3][j] + bias);
        float4 v1 = make_float4(acc[4][j] + bias, acc[5][j] + bias,
                                acc[6][j] + bias, acc[7][j] + bias);
        *(float4*)(dst)     = v0;
        *(float4*)(dst + 4) = v1;
    }
}

// ---------------------------------------------------------------------------
extern "C" void kernel_launch(void* const* d_in, const int* in_sizes, int n_in,
                              void* d_out, int out_size) {
    const float* x  = (const float*)d_in[0];
    const float* W1 = (const float*)d_in[1];
    const float* b1 = (const float*)d_in[2];
    const float* W2 = (const float*)d_in[3];
    const float* b2 = (const float*)d_in[4];
    float* y = (float*)d_out;

    const int smem_bytes = SMEM_FLOATS * (int)sizeof(float);   // 83584
    cudaFuncSetAttribute(attn_kernel,
                         cudaFuncAttributeMaxDynamicSharedMemorySize, smem_bytes);

    // 1) QKV projection: M=4096 pixels (x128), N=768 oc (x64), per batch
    qkv_gemm<<<dim3(PIX / 128, 768 / 64, BATCH), 256>>>(x, W1, b1);

    // 2) Attention: (64 windows, 8 heads, 16 batches)
    attn_kernel<<<dim3(NWIN * NWIN, NH, BATCH), 128, smem_bytes>>>();

    // 3) Output projection: M=4096 (x128), N=256 (x64), per batch
    proj_gemm<<<dim3(PIX / 128, CCH / 64, BATCH), 256>>>(W2, b2, y);
}

// round 2
// speedup vs baseline: 1.0846x; 1.0846x over previous
#include <cuda_runtime.h>
#include <math.h>

#define NH    8
#define EDIM  32
#define WS    8
#define MO    12
#define NKEY  (MO*MO)      // 144
#define BATCH 16
#define CCH   256
#define HH    64
#define WW    64
#define PIX   (HH*WW)      // 4096
#define NWIN  8

// Scratch buffers (allocation-free rule: __device__ globals)
__device__ float g_Q[BATCH * NH * PIX * EDIM];    // (b, head, pixel, e)
__device__ float g_K[BATCH * NH * PIX * EDIM];
__device__ float g_V[BATCH * NH * PIX * EDIM];
__device__ float g_att[BATCH * PIX * CCH];        // (b, pixel, c)

// ---- packed f32x2 helpers (sm_103a FFMA2 path: 2x fp32 FMA throughput) ----
typedef unsigned long long u64;

__device__ __forceinline__ u64 pack2(float lo, float hi) {
    u64 r; asm("mov.b64 %0, {%1, %2};" : "=l"(r) : "f"(lo), "f"(hi)); return r;
}
__device__ __forceinline__ u64 bcast2(float v) { return pack2(v, v); }
__device__ __forceinline__ float2 unpack2(u64 v) {
    float2 r; asm("mov.b64 {%0, %1}, %2;" : "=f"(r.x), "=f"(r.y) : "l"(v)); return r;
}
#define FMA2(d, a, b, c) \
    asm("fma.rn.f32x2 %0, %1, %2, %3;" : "=l"(d) : "l"(a), "l"(b), "l"(c))

// ---------------------------------------------------------------------------
// Kernel 1: QKV projection.  qkv[b,p,oc] = sum_c x[b,c,p] * W1[oc,c] + b1[oc]
// BM=128 pixels, BN=64 oc, BK=16, 256 threads, thread tile 8m x 4n as
// 4 m-pairs (f32x2) x 4 n.
// ---------------------------------------------------------------------------
__global__ __launch_bounds__(256) void qkv_gemm(const float* __restrict__ x,
                                                const float* __restrict__ W1,
                                                const float* __restrict__ b1) {
    __shared__ float As[16][128];   // [k][m]  row = 512B (16B aligned)
    __shared__ float Bs[16][68];    // [k][n]  row = 272B = 17*16B (16B aligned)

    const int b  = blockIdx.z;
    const int p0 = blockIdx.x * 128;
    const int n0 = blockIdx.y * 64;
    const int tid = threadIdx.x;
    const int tr = tid >> 4;   // 0..15 -> m base tr*8
    const int tc = tid & 15;   // 0..15 -> n base tc*4

    const float* xb = x + (size_t)b * CCH * PIX;

    u64 acc2[4][4];
#pragma unroll
    for (int i = 0; i < 4; i++)
#pragma unroll
        for (int j = 0; j < 4; j++) acc2[i][j] = 0ull;

    for (int c0 = 0; c0 < CCH; c0 += 16) {
        // A tile: 16 x 128 = 512 float4, 2 per thread
#pragma unroll
        for (int t = 0; t < 2; t++) {
            int idx = tid + t * 256;
            int kk  = idx >> 5;
            int mm  = (idx & 31) * 4;
            float4 v = *(const float4*)(xb + (size_t)(c0 + kk) * PIX + p0 + mm);
            As[kk][mm + 0] = v.x; As[kk][mm + 1] = v.y;
            As[kk][mm + 2] = v.z; As[kk][mm + 3] = v.w;
        }
        // B tile: 64 x 16 from W1 (contiguous in c=k), transposed store
        {
            int nn = tid >> 2;
            int kk = (tid & 3) * 4;
            float4 v = *(const float4*)(W1 + (size_t)(n0 + nn) * CCH + c0 + kk);
            Bs[kk + 0][nn] = v.x; Bs[kk + 1][nn] = v.y;
            Bs[kk + 2][nn] = v.z; Bs[kk + 3][nn] = v.w;
        }
        __syncthreads();

#pragma unroll
        for (int kk = 0; kk < 16; kk++) {
            u64 a2[4];
#pragma unroll
            for (int i = 0; i < 4; i++)
                a2[i] = *(const u64*)&As[kk][tr * 8 + 2 * i];
            float4 bf = *(const float4*)&Bs[kk][tc * 4];
            u64 b2[4] = { bcast2(bf.x), bcast2(bf.y), bcast2(bf.z), bcast2(bf.w) };
#pragma unroll
            for (int i = 0; i < 4; i++)
#pragma unroll
                for (int j = 0; j < 4; j++)
                    FMA2(acc2[i][j], a2[i], b2[j], acc2[i][j]);
        }
        __syncthreads();
    }

    // Epilogue: scatter into Q/K/V (b, head, pixel, e)
#pragma unroll
    for (int j = 0; j < 4; j++) {
        int oc   = n0 + tc * 4 + j;
        float bias = b1[oc];
        int type = oc % 3;
        int ch   = oc / 3;
        int head = ch >> 5;
        int e    = ch & 31;
        float* dst = (type == 0) ? g_Q : (type == 1) ? g_K : g_V;
        size_t base = ((size_t)(b * NH + head) * PIX) * EDIM + e;
#pragma unroll
        for (int i = 0; i < 4; i++) {
            int p = p0 + tr * 8 + 2 * i;
            float2 u = unpack2(acc2[i][j]);
            dst[base + (size_t)p * EDIM]       = u.x + bias;
            dst[base + (size_t)(p + 1) * EDIM] = u.y + bias;
        }
    }
}

// ---------------------------------------------------------------------------
// Kernel 2: windowed attention. One block (128 thr) per (b, head, window).
// 64 queries x 144 keys x E=32. Zero-padded OOB keys stay IN the softmax.
// ---------------------------------------------------------------------------
#define QS_STRIDE 34
#define KS_STRIDE 34
#define S_STRIDE  146
#define SMEM_FLOATS (64*QS_STRIDE + NKEY*KS_STRIDE + NKEY*KS_STRIDE + 64*S_STRIDE)

__global__ __launch_bounds__(128) void attn_kernel() {
    extern __shared__ float sm[];
    float* Qs = sm;                          // 64  x 34
    float* Ks = Qs + 64 * QS_STRIDE;         // 144 x 34
    float* Vs = Ks + NKEY * KS_STRIDE;       // 144 x 34
    float* S  = Vs + NKEY * KS_STRIDE;       // 64  x 146

    const int b    = blockIdx.z;
    const int head = blockIdx.y;
    const int wi   = blockIdx.x >> 3;
    const int wj   = blockIdx.x & 7;
    const int tid  = threadIdx.x;

    const size_t hb = (size_t)(b * NH + head) * PIX * EDIM;
    const float* Qg = g_Q + hb;
    const float* Kg = g_K + hb;
    const float* Vg = g_V + hb;

    // Load Q window (64 x 32)
    for (int idx = tid; idx < 64 * EDIM; idx += 128) {
        int q = idx >> 5, e = idx & 31;
        int r = wi * 8 + (q >> 3);
        int c = wj * 8 + (q & 7);
        Qs[q * QS_STRIDE + e] = Qg[(size_t)(r * WW + c) * EDIM + e];
    }
    // Load K/V halo (144 x 32), zero for OOB
    for (int idx = tid; idx < NKEY * EDIM; idx += 128) {
        int k = idx >> 5, e = idx & 31;
        int kr = k / MO, kc = k % MO;
        int r = wi * 8 - 2 + kr;
        int c = wj * 8 - 2 + kc;
        bool ok = (r >= 0) && (r < HH) && (c >= 0) && (c < WW);
        size_t off = (size_t)(r * WW + c) * EDIM + e;
        Ks[k * KS_STRIDE + e] = ok ? Kg[off] : 0.f;
        Vs[k * KS_STRIDE + e] = ok ? Vg[off] : 0.f;
    }
    __syncthreads();

    // Scores: thread tile = 8 queries (4 f32x2 pairs) x 9 keys
    {
        const int tq = tid >> 4;   // 0..7  -> q base tq*8
        const int tk = tid & 15;   // 0..15 -> k base tk*9
        u64 acc2[4][9];
#pragma unroll
        for (int i = 0; i < 4; i++)
#pragma unroll
            for (int j = 0; j < 9; j++) acc2[i][j] = 0ull;

        for (int e = 0; e < EDIM; e++) {
            u64 q2[4];
#pragma unroll
            for (int i = 0; i < 4; i++)
                q2[i] = pack2(Qs[(tq * 8 + 2 * i) * QS_STRIDE + e],
                              Qs[(tq * 8 + 2 * i + 1) * QS_STRIDE + e]);
            u64 k2[9];
#pragma unroll
            for (int j = 0; j < 9; j++)
                k2[j] = bcast2(Ks[(tk * 9 + j) * KS_STRIDE + e]);
#pragma unroll
            for (int i = 0; i < 4; i++)
#pragma unroll
                for (int j = 0; j < 9; j++)
                    FMA2(acc2[i][j], q2[i], k2[j], acc2[i][j]);
        }
        const float scale = 0.17677669529663687f;  // 1/sqrt(32)
#pragma unroll
        for (int i = 0; i < 4; i++)
#pragma unroll
            for (int j = 0; j < 9; j++) {
                float2 u = unpack2(acc2[i][j]);
                S[(tq * 8 + 2 * i)     * S_STRIDE + tk * 9 + j] = u.x * scale;
                S[(tq * 8 + 2 * i + 1) * S_STRIDE + tk * 9 + j] = u.y * scale;
            }
    }
    __syncthreads();

    // Softmax: 2 threads per row, 72 keys each, shfl reduction
    {
        const int row  = tid >> 1;
        const int half = tid & 1;
        float* r = S + row * S_STRIDE + half * 72;
        float m = -1e30f;
#pragma unroll 8
        for (int k = 0; k < 72; k++) m = fmaxf(m, r[k]);
        m = fmaxf(m, __shfl_xor_sync(0xFFFFFFFFu, m, 1));
        float s = 0.f;
#pragma unroll 8
        for (int k = 0; k < 72; k++) {
            float ex = __expf(r[k] - m);
            r[k] = ex;
            s += ex;
        }
        s += __shfl_xor_sync(0xFFFFFFFFu, s, 1);
        float inv = 1.f / s;
#pragma unroll 8
        for (int k = 0; k < 72; k++) r[k] *= inv;
    }
    __syncthreads();

    // out = A @ V : 64 x 32, thread tile 4 queries x 4 e (2 f32x2 e-pairs)
    {
        const int tq = tid >> 3;  // 0..15 -> q base tq*4
        const int te = tid & 7;   // 0..7  -> e base te*4
        u64 acc2[4][2];
#pragma unroll
        for (int i = 0; i < 4; i++) { acc2[i][0] = 0ull; acc2[i][1] = 0ull; }

        for (int k = 0; k < NKEY; k++) {
            u64 a2[4];
#pragma unroll
            for (int i = 0; i < 4; i++)
                a2[i] = bcast2(S[(tq * 4 + i) * S_STRIDE + k]);
            u64 v0 = *(const u64*)&Vs[k * KS_STRIDE + te * 4];
            u64 v1 = *(const u64*)&Vs[k * KS_STRIDE + te * 4 + 2];
#pragma unroll
            for (int i = 0; i < 4; i++) {
                FMA2(acc2[i][0], a2[i], v0, acc2[i][0]);
                FMA2(acc2[i][1], a2[i], v1, acc2[i][1]);
            }
        }
        // Write to g_att[b][pixel][head*32 + e]
#pragma unroll
        for (int i = 0; i < 4; i++) {
            int q = tq * 4 + i;
            int r = wi * 8 + (q >> 3);
            int c = wj * 8 + (q & 7);
            float2 u0 = unpack2(acc2[i][0]);
            float2 u1 = unpack2(acc2[i][1]);
            float4 v4 = make_float4(u0.x, u0.y, u1.x, u1.y);
            *(float4*)(g_att + ((size_t)b * PIX + r * WW + c) * CCH
                       + head * EDIM + te * 4) = v4;
        }
    }
}

// ---------------------------------------------------------------------------
// Kernel 3: output projection. y[b,n,p] = sum_c att[b,p,c]*W2[n,c] + b2[n]
// ---------------------------------------------------------------------------
__global__ __launch_bounds__(256) void proj_gemm(const float* __restrict__ W2,
                                                 const float* __restrict__ b2,
                                                 float* __restrict__ y) {
    __shared__ float As[16][132];   // [k][m] row = 528B = 33*16B (aligned)
    __shared__ float Bs[16][68];    // [k][n]

    const int b  = blockIdx.z;
    const int p0 = blockIdx.x * 128;
    const int n0 = blockIdx.y * 64;
    const int tid = threadIdx.x;
    const int tr = tid >> 4;
    const int tc = tid & 15;

    const float* ab = g_att + (size_t)b * PIX * CCH;

    u64 acc2[4][4];
#pragma unroll
    for (int i = 0; i < 4; i++)
#pragma unroll
        for (int j = 0; j < 4; j++) acc2[i][j] = 0ull;

    for (int c0 = 0; c0 < CCH; c0 += 16) {
        // A tile: 128 pixels x 16 c (att contiguous in c) -> transposed store
#pragma unroll
        for (int t = 0; t < 2; t++) {
            int idx = tid + t * 256;
            int mm  = idx >> 2;
            int kk  = (idx & 3) * 4;
            float4 v = *(const float4*)(ab + (size_t)(p0 + mm) * CCH + c0 + kk);
            As[kk + 0][mm] = v.x; As[kk + 1][mm] = v.y;
            As[kk + 2][mm] = v.z; As[kk + 3][mm] = v.w;
        }
        // B tile: 64 x 16 from W2
        {
            int nn = tid >> 2;
            int kk = (tid & 3) * 4;
            float4 v = *(const float4*)(W2 + (size_t)(n0 + nn) * CCH + c0 + kk);
            Bs[kk + 0][nn] = v.x; Bs[kk + 1][nn] = v.y;
            Bs[kk + 2][nn] = v.z; Bs[kk + 3][nn] = v.w;
        }
        __syncthreads();

#pragma unroll
        for (int kk = 0; kk < 16; kk++) {
            u64 a2[4];
#pragma unroll
            for (int i = 0; i < 4; i++)
                a2[i] = *(const u64*)&As[kk][tr * 8 + 2 * i];
            float4 bf = *(const float4*)&Bs[kk][tc * 4];
            u64 b2v[4] = { bcast2(bf.x), bcast2(bf.y), bcast2(bf.z), bcast2(bf.w) };
#pragma unroll
            for (int i = 0; i < 4; i++)
#pragma unroll
                for (int j = 0; j < 4; j++)
                    FMA2(acc2[i][j], a2[i], b2v[j], acc2[i][j]);
        }
        __syncthreads();
    }

    // Output: y[b][n][p], contiguous in p -> float4 stores
#pragma unroll
    for (int j = 0; j < 4; j++) {
        int n = n0 + tc * 4 + j;
        float bias = b2[n];
        float* dst = y + ((size_t)(b * CCH + n)) * PIX + p0 + tr * 8;
        float2 u0 = unpack2(acc2[0][j]);
        float2 u1 = unpack2(acc2[1][j]);
        float2 u2 = unpack2(acc2[2][j]);
        float2 u3 = unpack2(acc2[3][j]);
        float4 v0 = make_float4(u0.x + bias, u0.y + bias, u1.x + bias, u1.y + bias);
        float4 v1 = make_float4(u2.x + bias, u2.y + bias, u3.x + bias, u3.y + bias);
        *(float4*)(dst)     = v0;
        *(float4*)(dst + 4) = v1;
    }
}

// ---------------------------------------------------------------------------
extern "C" void kernel_launch(void* const* d_in, const int* in_sizes, int n_in,
                              void* d_out, int out_size) {
    const float* x  = (const float*)d_in[0];
    const float* W1 = (const float*)d_in[1];
    const float* b1 = (const float*)d_in[2];
    const float* W2 = (const float*)d_in[3];
    const float* b2 = (const float*)d_in[4];
    float* y = (float*)d_out;

    const int smem_bytes = SMEM_FLOATS * (int)sizeof(float);   // 85248
    cudaFuncSetAttribute(attn_kernel,
                         cudaFuncAttributeMaxDynamicSharedMemorySize, smem_bytes);

    // 1) QKV projection: M=4096 pixels (x128), N=768 oc (x64), per batch
    qkv_gemm<<<dim3(PIX / 128, 768 / 64, BATCH), 256>>>(x, W1, b1);

    // 2) Attention: (64 windows, 8 heads, 16 batches)
    attn_kernel<<<dim3(NWIN * NWIN, NH, BATCH), 128, smem_bytes>>>();

    // 3) Output projection: M=4096 (x128), N=256 (x64), per batch
    proj_gemm<<<dim3(PIX / 128, CCH / 64, BATCH), 256>>>(W2, b2, y);
}

// round 3
// speedup vs baseline: 1.1162x; 1.0291x over previous
#include <cuda_runtime.h>
#include <math.h>

#define NH    8
#define EDIM  32
#define WS    8
#define MO    12
#define NKEY  (MO*MO)      // 144
#define NKPAD 160          // padded keys (zeros, masked from softmax)
#define BATCH 16
#define CCH   256
#define HH    64
#define WW    64
#define PIX   (HH*WW)      // 4096
#define NWIN  8

// Scratch buffers (allocation-free rule: __device__ globals)
__device__ float g_Q[BATCH * NH * PIX * EDIM];    // (b, head, pixel, e)
__device__ float g_K[BATCH * NH * PIX * EDIM];
__device__ float g_V[BATCH * NH * PIX * EDIM];
__device__ float g_att[BATCH * PIX * CCH];        // (b, pixel, c)

// ---- packed f32x2 helpers ----
typedef unsigned long long u64;

__device__ __forceinline__ u64 pack2(float lo, float hi) {
    u64 r; asm("mov.b64 %0, {%1, %2};" : "=l"(r) : "f"(lo), "f"(hi)); return r;
}
__device__ __forceinline__ u64 bcast2(float v) { return pack2(v, v); }
__device__ __forceinline__ float2 unpack2(u64 v) {
    float2 r; asm("mov.b64 {%0, %1}, %2;" : "=f"(r.x), "=f"(r.y) : "l"(v)); return r;
}
#define FMA2(d, a, b, c) \
    asm("fma.rn.f32x2 %0, %1, %2, %3;" : "=l"(d) : "l"(a), "l"(b), "l"(c))

// ---------------------------------------------------------------------------
// Kernel 1: QKV projection. BM=128 pixels, BN=128 oc, BK=16, 256 threads,
// thread tile 8m x 8n (n-fragment split tc*4 / tc*4+64 for bank-friendly LDS.128)
// ---------------------------------------------------------------------------
__global__ __launch_bounds__(256) void qkv_gemm(const float* __restrict__ x,
                                                const float* __restrict__ W1,
                                                const float* __restrict__ b1) {
    __shared__ float As[16][128];   // [k][m]
    __shared__ float Bs[16][132];   // [k][n], padded

    const int b  = blockIdx.z;
    const int p0 = blockIdx.x * 128;
    const int n0 = blockIdx.y * 128;
    const int tid = threadIdx.x;
    const int tr = tid >> 4;   // 0..15 -> m base tr*8
    const int tc = tid & 15;   // 0..15 -> n frags tc*4 and tc*4+64

    const float* xb = x + (size_t)b * CCH * PIX;

    u64 acc2[4][8];
#pragma unroll
    for (int i = 0; i < 4; i++)
#pragma unroll
        for (int j = 0; j < 8; j++) acc2[i][j] = 0ull;

    for (int c0 = 0; c0 < CCH; c0 += 16) {
        // A tile: 16 x 128 = 512 float4, 2 per thread
#pragma unroll
        for (int t = 0; t < 2; t++) {
            int idx = tid + t * 256;
            int kk  = idx >> 5;
            int mm  = (idx & 31) * 4;
            float4 v = *(const float4*)(xb + (size_t)(c0 + kk) * PIX + p0 + mm);
            As[kk][mm + 0] = v.x; As[kk][mm + 1] = v.y;
            As[kk][mm + 2] = v.z; As[kk][mm + 3] = v.w;
        }
        // B tile: 128 oc x 16 k from W1 (contiguous in c=k), transposed store
#pragma unroll
        for (int t = 0; t < 2; t++) {
            int idx = tid + t * 256;
            int nn = idx >> 2;                // 0..127
            int kk = (idx & 3) * 4;
            float4 v = *(const float4*)(W1 + (size_t)(n0 + nn) * CCH + c0 + kk);
            Bs[kk + 0][nn] = v.x; Bs[kk + 1][nn] = v.y;
            Bs[kk + 2][nn] = v.z; Bs[kk + 3][nn] = v.w;
        }
        __syncthreads();

#pragma unroll
        for (int kk = 0; kk < 16; kk++) {
            u64 a2[4];
#pragma unroll
            for (int i = 0; i < 4; i++)
                a2[i] = *(const u64*)&As[kk][tr * 8 + 2 * i];
            float4 bl = *(const float4*)&Bs[kk][tc * 4];
            float4 bh = *(const float4*)&Bs[kk][tc * 4 + 64];
            u64 bb[8] = { bcast2(bl.x), bcast2(bl.y), bcast2(bl.z), bcast2(bl.w),
                          bcast2(bh.x), bcast2(bh.y), bcast2(bh.z), bcast2(bh.w) };
#pragma unroll
            for (int i = 0; i < 4; i++)
#pragma unroll
                for (int j = 0; j < 8; j++)
                    FMA2(acc2[i][j], a2[i], bb[j], acc2[i][j]);
        }
        __syncthreads();
    }

    // Epilogue: scatter into Q/K/V (b, head, pixel, e)
#pragma unroll
    for (int j = 0; j < 8; j++) {
        int nn   = tc * 4 + (j & 3) + (j >> 2) * 64;
        int oc   = n0 + nn;
        float bias = b1[oc];
        int type = oc % 3;
        int ch   = oc / 3;
        int head = ch >> 5;
        int e    = ch & 31;
        float* dst = (type == 0) ? g_Q : (type == 1) ? g_K : g_V;
        size_t base = ((size_t)(b * NH + head) * PIX) * EDIM + e;
#pragma unroll
        for (int i = 0; i < 4; i++) {
            int p = p0 + tr * 8 + 2 * i;
            float2 u = unpack2(acc2[i][j]);
            dst[base + (size_t)p * EDIM]       = u.x + bias;
            dst[base + (size_t)(p + 1) * EDIM] = u.y + bias;
        }
    }
}

// ---------------------------------------------------------------------------
// Kernel 2: windowed attention. One block (128 thr) per (b, head, window).
// Q,K transposed in smem ([e][idx]); K padded to 160 keys (zeros, masked).
// ---------------------------------------------------------------------------
#define QT_STRIDE 66
#define KT_STRIDE 162
#define VS_STRIDE 34
#define S_STRIDE  162
#define SMEM_FLOATS (EDIM*QT_STRIDE + EDIM*KT_STRIDE + NKEY*VS_STRIDE + 64*S_STRIDE)

__global__ __launch_bounds__(128) void attn_kernel() {
    extern __shared__ float sm[];
    float* Qt = sm;                          // 32 x 66   [e][q]
    float* Kt = Qt + EDIM * QT_STRIDE;       // 32 x 162  [e][k] (160 used)
    float* Vs = Kt + EDIM * KT_STRIDE;       // 144 x 34  [k][e]
    float* S  = Vs + NKEY * VS_STRIDE;       // 64 x 162  (160 cols used)

    const int b    = blockIdx.z;
    const int head = blockIdx.y;
    const int wi   = blockIdx.x >> 3;
    const int wj   = blockIdx.x & 7;
    const int tid  = threadIdx.x;

    const size_t hb = (size_t)(b * NH + head) * PIX * EDIM;
    const float* Qg = g_Q + hb;
    const float* Kg = g_K + hb;
    const float* Vg = g_V + hb;

    // Zero K pad region (k = 144..159 for all e)
    for (int idx = tid; idx < EDIM * (NKPAD - NKEY); idx += 128) {
        int e = idx >> 4, k = NKEY + (idx & 15);
        Kt[e * KT_STRIDE + k] = 0.f;
    }
    // Load Q window (64 x 32) transposed
    for (int idx = tid; idx < 64 * EDIM; idx += 128) {
        int q = idx >> 5, e = idx & 31;
        int r = wi * 8 + (q >> 3);
        int c = wj * 8 + (q & 7);
        Qt[e * QT_STRIDE + q] = Qg[(size_t)(r * WW + c) * EDIM + e];
    }
    // Load K halo transposed, V halo row-major; zero for OOB
    for (int idx = tid; idx < NKEY * EDIM; idx += 128) {
        int k = idx >> 5, e = idx & 31;
        int kr = k / MO, kc = k % MO;
        int r = wi * 8 - 2 + kr;
        int c = wj * 8 - 2 + kc;
        bool ok = (r >= 0) && (r < HH) && (c >= 0) && (c < WW);
        size_t off = (size_t)(r * WW + c) * EDIM + e;
        Kt[e * KT_STRIDE + k] = ok ? Kg[off] : 0.f;
        Vs[k * VS_STRIDE + e] = ok ? Vg[off] : 0.f;
    }
    __syncthreads();

    // Scores: thread tile = 8 queries x 10 keys (5 k-pairs, FMA2 over k)
    {
        const int tq = tid >> 4;   // 0..7  -> q base tq*8
        const int tk = tid & 15;   // 0..15 -> k base tk*10
        u64 acc2[8][5];
#pragma unroll
        for (int i = 0; i < 8; i++)
#pragma unroll
            for (int j = 0; j < 5; j++) acc2[i][j] = 0ull;

#pragma unroll 4
        for (int e = 0; e < EDIM; e++) {
            const float* qrow = Qt + e * QT_STRIDE + tq * 8;
            const float* krow = Kt + e * KT_STRIDE + tk * 10;
            u64 qb[8];
#pragma unroll
            for (int i = 0; i < 4; i++) {
                float2 qp = *(const float2*)(qrow + 2 * i);
                qb[2 * i]     = bcast2(qp.x);
                qb[2 * i + 1] = bcast2(qp.y);
            }
            u64 k2[5];
#pragma unroll
            for (int j = 0; j < 5; j++)
                k2[j] = *(const u64*)(krow + 2 * j);
#pragma unroll
            for (int i = 0; i < 8; i++)
#pragma unroll
                for (int j = 0; j < 5; j++)
                    FMA2(acc2[i][j], qb[i], k2[j], acc2[i][j]);
        }
        const float scale = 0.17677669529663687f;  // 1/sqrt(32)
#pragma unroll
        for (int i = 0; i < 8; i++)
#pragma unroll
            for (int j = 0; j < 5; j++) {
                float2 u = unpack2(acc2[i][j]);
                *(float2*)&S[(tq * 8 + i) * S_STRIDE + tk * 10 + 2 * j] =
                    make_float2(u.x * scale, u.y * scale);
            }
    }
    __syncthreads();

    // Softmax over first 144 cols: 2 threads per row, 72 keys each
    {
        const int row  = tid >> 1;
        const int half = tid & 1;
        float* r = S + row * S_STRIDE + half * 72;
        float m = -1e30f;
#pragma unroll 8
        for (int k = 0; k < 72; k++) m = fmaxf(m, r[k]);
        m = fmaxf(m, __shfl_xor_sync(0xFFFFFFFFu, m, 1));
        float s = 0.f;
#pragma unroll 8
        for (int k = 0; k < 72; k++) {
            float ex = __expf(r[k] - m);
            r[k] = ex;
            s += ex;
        }
        s += __shfl_xor_sync(0xFFFFFFFFu, s, 1);
        float inv = 1.f / s;
#pragma unroll 8
        for (int k = 0; k < 72; k++) r[k] *= inv;
    }
    __syncthreads();

    // out = A @ V : 64 x 32, thread tile 4 queries x 4 e (2 f32x2 e-pairs)
    {
        const int tq = tid >> 3;  // 0..15 -> q base tq*4
        const int te = tid & 7;   // 0..7  -> e base te*4
        u64 acc2[4][2];
#pragma unroll
        for (int i = 0; i < 4; i++) { acc2[i][0] = 0ull; acc2[i][1] = 0ull; }

#pragma unroll 4
        for (int k = 0; k < NKEY; k++) {
            u64 a2[4];
#pragma unroll
            for (int i = 0; i < 4; i++)
                a2[i] = bcast2(S[(tq * 4 + i) * S_STRIDE + k]);
            u64 v0 = *(const u64*)&Vs[k * VS_STRIDE + te * 4];
            u64 v1 = *(const u64*)&Vs[k * VS_STRIDE + te * 4 + 2];
#pragma unroll
            for (int i = 0; i < 4; i++) {
                FMA2(acc2[i][0], a2[i], v0, acc2[i][0]);
                FMA2(acc2[i][1], a2[i], v1, acc2[i][1]);
            }
        }
        // Write to g_att[b][pixel][head*32 + e]
#pragma unroll
        for (int i = 0; i < 4; i++) {
            int q = tq * 4 + i;
            int r = wi * 8 + (q >> 3);
            int c = wj * 8 + (q & 7);
            float2 u0 = unpack2(acc2[i][0]);
            float2 u1 = unpack2(acc2[i][1]);
            float4 v4 = make_float4(u0.x, u0.y, u1.x, u1.y);
            *(float4*)(g_att + ((size_t)b * PIX + r * WW + c) * CCH
                       + head * EDIM + te * 4) = v4;
        }
    }
}

// ---------------------------------------------------------------------------
// Kernel 3: output projection. BM=128, BN=128, BK=16, thread tile 8x8.
// ---------------------------------------------------------------------------
__global__ __launch_bounds__(256) void proj_gemm(const float* __restrict__ W2,
                                                 const float* __restrict__ b2,
                                                 float* __restrict__ y) {
    __shared__ float As[16][132];   // [k][m] padded (transposed stores)
    __shared__ float Bs[16][132];   // [k][n]

    const int b  = blockIdx.z;
    const int p0 = blockIdx.x * 128;
    const int n0 = blockIdx.y * 128;
    const int tid = threadIdx.x;
    const int tr = tid >> 4;
    const int tc = tid & 15;

    const float* ab = g_att + (size_t)b * PIX * CCH;

    u64 acc2[4][8];
#pragma unroll
    for (int i = 0; i < 4; i++)
#pragma unroll
        for (int j = 0; j < 8; j++) acc2[i][j] = 0ull;

    for (int c0 = 0; c0 < CCH; c0 += 16) {
        // A tile: 128 pixels x 16 c (att contiguous in c) -> transposed store
#pragma unroll
        for (int t = 0; t < 2; t++) {
            int idx = tid + t * 256;
            int mm  = idx >> 2;
            int kk  = (idx & 3) * 4;
            float4 v = *(const float4*)(ab + (size_t)(p0 + mm) * CCH + c0 + kk);
            As[kk + 0][mm] = v.x; As[kk + 1][mm] = v.y;
            As[kk + 2][mm] = v.z; As[kk + 3][mm] = v.w;
        }
        // B tile: 128 oc x 16 k from W2, transposed store
#pragma unroll
        for (int t = 0; t < 2; t++) {
            int idx = tid + t * 256;
            int nn = idx >> 2;
            int kk = (idx & 3) * 4;
            float4 v = *(const float4*)(W2 + (size_t)(n0 + nn) * CCH + c0 + kk);
            Bs[kk + 0][nn] = v.x; Bs[kk + 1][nn] = v.y;
            Bs[kk + 2][nn] = v.z; Bs[kk + 3][nn] = v.w;
        }
        __syncthreads();

#pragma unroll
        for (int kk = 0; kk < 16; kk++) {
            u64 a2[4];
#pragma unroll
            for (int i = 0; i < 4; i++)
                a2[i] = *(const u64*)&As[kk][tr * 8 + 2 * i];
            float4 bl = *(const float4*)&Bs[kk][tc * 4];
            float4 bh = *(const float4*)&Bs[kk][tc * 4 + 64];
            u64 bb[8] = { bcast2(bl.x), bcast2(bl.y), bcast2(bl.z), bcast2(bl.w),
                          bcast2(bh.x), bcast2(bh.y), bcast2(bh.z), bcast2(bh.w) };
#pragma unroll
            for (int i = 0; i < 4; i++)
#pragma unroll
                for (int j = 0; j < 8; j++)
                    FMA2(acc2[i][j], a2[i], bb[j], acc2[i][j]);
        }
        __syncthreads();
    }

    // Output: y[b][n][p], contiguous in p -> float4 stores
#pragma unroll
    for (int j = 0; j < 8; j++) {
        int nn = tc * 4 + (j & 3) + (j >> 2) * 64;
        int n  = n0 + nn;
        float bias = b2[n];
        float* dst = y + ((size_t)(b * CCH + n)) * PIX + p0 + tr * 8;
        float2 u0 = unpack2(acc2[0][j]);
        float2 u1 = unpack2(acc2[1][j]);
        float2 u2 = unpack2(acc2[2][j]);
        float2 u3 = unpack2(acc2[3][j]);
        float4 v0 = make_float4(u0.x + bias, u0.y + bias, u1.x + bias, u1.y + bias);
        float4 v1 = make_float4(u2.x + bias, u2.y + bias, u3.x + bias, u3.y + bias);
        *(float4*)(dst)     = v0;
        *(float4*)(dst + 4) = v1;
    }
}

// ---------------------------------------------------------------------------
extern "C" void kernel_launch(void* const* d_in, const int* in_sizes, int n_in,
                              void* d_out, int out_size) {
    const float* x  = (const float*)d_in[0];
    const float* W1 = (const float*)d_in[1];
    const float* b1 = (const float*)d_in[2];
    const float* W2 = (const float*)d_in[3];
    const float* b2 = (const float*)d_in[4];
    float* y = (float*)d_out;

    const int smem_bytes = SMEM_FLOATS * (int)sizeof(float);
    cudaFuncSetAttribute(attn_kernel,
                         cudaFuncAttributeMaxDynamicSharedMemorySize, smem_bytes);

    // 1) QKV projection: M=4096 (x128), N=768 (x128), per batch
    qkv_gemm<<<dim3(PIX / 128, 768 / 128, BATCH), 256>>>(x, W1, b1);

    // 2) Attention: (64 windows, 8 heads, 16 batches)
    attn_kernel<<<dim3(NWIN * NWIN, NH, BATCH), 128, smem_bytes>>>();

    // 3) Output projection: M=4096 (x128), N=256 (x128), per batch
    proj_gemm<<<dim3(PIX / 128, CCH / 128, BATCH), 256>>>(W2, b2, y);
}

// round 7
// speedup vs baseline: 1.3049x; 1.1691x over previous
#include <cuda_runtime.h>
#include <cuda_bf16.h>
#include <math.h>

#define NH    8
#define EDIM  32
#define WS    8
#define MO    12
#define NKEY  (MO*MO)      // 144
#define NKPAD 160
#define BATCH 16
#define CCH   256
#define HH    64
#define WW    64
#define PIX   (HH*WW)      // 4096
#define NWIN  8

typedef unsigned long long u64;
typedef unsigned int u32;

// Scratch buffers
__device__ float g_Q[BATCH * NH * PIX * EDIM];    // (b, head, pixel, e)
__device__ float g_K[BATCH * NH * PIX * EDIM];
__device__ float g_V[BATCH * NH * PIX * EDIM];
__device__ float g_att[BATCH * PIX * CCH];        // (b, pixel, c)

// bf16 hi/lo split scratch
__device__ __nv_bfloat16 g_xh[BATCH * PIX * CCH];   // x transposed: (b, p, c)
__device__ __nv_bfloat16 g_xl[BATCH * PIX * CCH];
__device__ __nv_bfloat16 g_w1h[768 * CCH];          // (n, k)
__device__ __nv_bfloat16 g_w1l[768 * CCH];
__device__ __nv_bfloat16 g_w2h[CCH * CCH];
__device__ __nv_bfloat16 g_w2l[CCH * CCH];

// ---- packed f32x2 helpers (attn kernel) ----
__device__ __forceinline__ u64 pack2(float lo, float hi) {
    u64 r; asm("mov.b64 %0, {%1, %2};" : "=l"(r) : "f"(lo), "f"(hi)); return r;
}
__device__ __forceinline__ u64 bcast2(float v) { return pack2(v, v); }
__device__ __forceinline__ float2 unpack2(u64 v) {
    float2 r; asm("mov.b64 {%0, %1}, %2;" : "=f"(r.x), "=f"(r.y) : "l"(v)); return r;
}
#define FMA2(d, a, b, c) \
    asm("fma.rn.f32x2 %0, %1, %2, %3;" : "=l"(d) : "l"(a), "l"(b), "l"(c))

// ---- mma.sync helpers (baseline PTX, compiles for plain sm_103) ----
__device__ __forceinline__ u32 smem_u32(const void* p) {
    u32 a; asm("{ .reg .u64 t; cvta.to.shared.u64 t, %1; cvt.u32.u64 %0, t; }"
               : "=r"(a) : "l"(p));
    return a;
}
__device__ __forceinline__ void ldsm4(u32* r, u32 addr) {
    asm volatile("ldmatrix.sync.aligned.m8n8.x4.shared.b16 {%0,%1,%2,%3}, [%4];"
                 : "=r"(r[0]), "=r"(r[1]), "=r"(r[2]), "=r"(r[3]) : "r"(addr));
}
__device__ __forceinline__ void mma_bf16(float* d, const u32* a, const u32* b) {
    asm volatile(
        "mma.sync.aligned.m16n8k16.row.col.f32.bf16.bf16.f32 "
        "{%0,%1,%2,%3}, {%4,%5,%6,%7}, {%8,%9}, {%0,%1,%2,%3};"
        : "+f"(d[0]), "+f"(d[1]), "+f"(d[2]), "+f"(d[3])
        : "r"(a[0]), "r"(a[1]), "r"(a[2]), "r"(a[3]), "r"(b[0]), "r"(b[1]));
}

// GEMM smem: 4 bf16 arrays of 128 rows x 72 (64 used, pad->144B rows)
#define KPAD 72
#define TILE_B (128 * KPAD * 2)       // 18432 bytes
#define GEMM_SMEM (4 * TILE_B)        // 73728 bytes

// ---------------------------------------------------------------------------
// Conversion kernels: split fp32 into bf16 hi + lo once.
// ---------------------------------------------------------------------------
__global__ void conv_x(const float* __restrict__ x) {
    __shared__ float tile[32][33];
    const int b  = blockIdx.z;
    const int p0 = blockIdx.x * 32;
    const int c0 = blockIdx.y * 32;
    const int tx = threadIdx.x, ty = threadIdx.y;   // 32 x 8
    const float* xb = x + ((size_t)b * CCH + c0) * PIX + p0;
#pragma unroll
    for (int i = 0; i < 32; i += 8)
        tile[ty + i][tx] = xb[(size_t)(ty + i) * PIX + tx];
    __syncthreads();
#pragma unroll
    for (int i = 0; i < 32; i += 8) {
        int p = p0 + ty + i;
        float v = tile[tx][ty + i];
        __nv_bfloat16 hi = __float2bfloat16(v);
        __nv_bfloat16 lo = __float2bfloat16(v - __bfloat162float(hi));
        size_t o = ((size_t)b * PIX + p) * CCH + c0 + tx;
        g_xh[o] = hi;
        g_xl[o] = lo;
    }
}

__global__ void conv_w(const float* __restrict__ w, __nv_bfloat16* __restrict__ wh,
                       __nv_bfloat16* __restrict__ wl, int n) {
    int i = blockIdx.x * 256 + threadIdx.x;
    if (i < n) {
        float v = w[i];
        __nv_bfloat16 hi = __float2bfloat16(v);
        __nv_bfloat16 lo = __float2bfloat16(v - __bfloat162float(hi));
        wh[i] = hi;
        wl[i] = lo;
    }
}

// ---------------------------------------------------------------------------
// Kernel 1: QKV projection via mma.sync bf16x3.
// D[m][n] = sum_k x[b][k][p0+m] * W1[n0+n][k], A from pre-transposed g_xh/l.
// Block 256 thr = 8 warps (4 m x 2 n); warp = 32m x 64n; K chunks of 64.
// ---------------------------------------------------------------------------
__global__ __launch_bounds__(256) void qkv_mma(const float* __restrict__ b1) {
    extern __shared__ char smem[];
    char* sAh = smem;
    char* sAl = smem + TILE_B;
    char* sBh = smem + 2 * TILE_B;
    char* sBl = smem + 3 * TILE_B;
    const u32 uAh = smem_u32(sAh), uAl = smem_u32(sAl);
    const u32 uBh = smem_u32(sBh), uBl = smem_u32(sBl);

    const int tid = threadIdx.x;
    const int lane = tid & 31, wid = tid >> 5;
    const int warp_m = wid >> 1, warp_n = wid & 1;
    const int b  = blockIdx.z;
    const int p0 = blockIdx.x * 128;
    const int n0 = blockIdx.y * 128;

    const int g = lane >> 3, rr = lane & 7;
    const u32 offA = (u32)(((warp_m * 32 + rr + (g & 1) * 8) * KPAD + (g >> 1) * 8) * 2);
    const u32 offB = (u32)(((warp_n * 64 + (g >> 1) * 8 + rr) * KPAD + (g & 1) * 8) * 2);

    float acc[2][8][4];
#pragma unroll
    for (int ma = 0; ma < 2; ma++)
#pragma unroll
        for (int na = 0; na < 8; na++)
#pragma unroll
            for (int v = 0; v < 4; v++) acc[ma][na][v] = 0.f;

    const __nv_bfloat16* Ah = g_xh + (size_t)b * PIX * CCH;
    const __nv_bfloat16* Al = g_xl + (size_t)b * PIX * CCH;

    for (int c0 = 0; c0 < CCH; c0 += 64) {
        // A: 128 rows x 64 k, contiguous k -> int4 (8 bf16) copies
#pragma unroll
        for (int t = 0; t < 4; t++) {
            int idx = tid + t * 256;          // 0..1023
            int row = idx >> 3, seg = idx & 7;
            size_t src = ((size_t)(p0 + row)) * CCH + c0 + seg * 8;
            int doff = row * (KPAD * 2) + seg * 16;
            *(int4*)(sAh + doff) = *(const int4*)(Ah + src);
            *(int4*)(sAl + doff) = *(const int4*)(Al + src);
        }
        // B: 128 rows x 64 k from W1 hi/lo
#pragma unroll
        for (int t = 0; t < 4; t++) {
            int idx = tid + t * 256;
            int row = idx >> 3, seg = idx & 7;
            size_t src = ((size_t)(n0 + row)) * CCH + c0 + seg * 8;
            int doff = row * (KPAD * 2) + seg * 16;
            *(int4*)(sBh + doff) = *(const int4*)(g_w1h + src);
            *(int4*)(sBl + doff) = *(const int4*)(g_w1l + src);
        }
        __syncthreads();

#pragma unroll
        for (int ks = 0; ks < 4; ks++) {
            const u32 ko = ks * 32;           // 16 k * 2 bytes
            u32 ah[2][4], al[2][4];
            ldsm4(ah[0], uAh + offA + ko);
            ldsm4(ah[1], uAh + offA + ko + 16 * KPAD * 2);
            ldsm4(al[0], uAl + offA + ko);
            ldsm4(al[1], uAl + offA + ko + 16 * KPAD * 2);
#pragma unroll
            for (int ng = 0; ng < 4; ng++) {
                u32 bh[4], bl[4];
                ldsm4(bh, uBh + offB + ko + ng * (16 * KPAD * 2));
                ldsm4(bl, uBl + offB + ko + ng * (16 * KPAD * 2));
#pragma unroll
                for (int h = 0; h < 2; h++) {   // two n-atoms in this group
                    const u32* bhf = bh + 2 * h;
                    const u32* blf = bl + 2 * h;
                    int na = ng * 2 + h;
#pragma unroll
                    for (int ma = 0; ma < 2; ma++) {
                        mma_bf16(acc[ma][na], ah[ma], bhf);
                        mma_bf16(acc[ma][na], ah[ma], blf);
                        mma_bf16(acc[ma][na], al[ma], bhf);
                    }
                }
            }
        }
        __syncthreads();
    }

    // Epilogue: scatter into Q/K/V
    const int r = lane >> 2;
    const int cp = (lane & 3) * 2;
#pragma unroll
    for (int ma = 0; ma < 2; ma++) {
#pragma unroll
        for (int na = 0; na < 8; na++) {
#pragma unroll
            for (int v = 0; v < 4; v++) {
                int m  = p0 + warp_m * 32 + ma * 16 + r + (v >> 1) * 8;
                int oc = n0 + warp_n * 64 + na * 8 + cp + (v & 1);
                float val = acc[ma][na][v] + b1[oc];
                int type = oc % 3;
                int ch   = oc / 3;
                int head = ch >> 5;
                int e    = ch & 31;
                float* dst = (type == 0) ? g_Q : (type == 1) ? g_K : g_V;
                dst[((size_t)(b * NH + head) * PIX + m) * EDIM + e] = val;
            }
        }
    }
}

// ---------------------------------------------------------------------------
// Kernel 2: windowed attention (fp32 FFMA2, unchanged — passing since R3)
// ---------------------------------------------------------------------------
#define QT_STRIDE 66
#define KT_STRIDE 162
#define VS_STRIDE 34
#define S_STRIDE  162
#define SMEM_FLOATS (EDIM*QT_STRIDE + EDIM*KT_STRIDE + NKEY*VS_STRIDE + 64*S_STRIDE)

__global__ __launch_bounds__(128) void attn_kernel() {
    extern __shared__ float sm[];
    float* Qt = sm;                          // 32 x 66   [e][q]
    float* Kt = Qt + EDIM * QT_STRIDE;       // 32 x 162  [e][k]
    float* Vs = Kt + EDIM * KT_STRIDE;       // 144 x 34  [k][e]
    float* S  = Vs + NKEY * VS_STRIDE;       // 64 x 162

    const int b    = blockIdx.z;
    const int head = blockIdx.y;
    const int wi   = blockIdx.x >> 3;
    const int wj   = blockIdx.x & 7;
    const int tid  = threadIdx.x;

    const size_t hb = (size_t)(b * NH + head) * PIX * EDIM;
    const float* Qg = g_Q + hb;
    const float* Kg = g_K + hb;
    const float* Vg = g_V + hb;

    for (int idx = tid; idx < EDIM * (NKPAD - NKEY); idx += 128) {
        int e = idx >> 4, k = NKEY + (idx & 15);
        Kt[e * KT_STRIDE + k] = 0.f;
    }
    for (int idx = tid; idx < 64 * EDIM; idx += 128) {
        int q = idx >> 5, e = idx & 31;
        int r = wi * 8 + (q >> 3);
        int c = wj * 8 + (q & 7);
        Qt[e * QT_STRIDE + q] = Qg[(size_t)(r * WW + c) * EDIM + e];
    }
    for (int idx = tid; idx < NKEY * EDIM; idx += 128) {
        int k = idx >> 5, e = idx & 31;
        int kr = k / MO, kc = k % MO;
        int r = wi * 8 - 2 + kr;
        int c = wj * 8 - 2 + kc;
        bool ok = (r >= 0) && (r < HH) && (c >= 0) && (c < WW);
        size_t off = (size_t)(r * WW + c) * EDIM + e;
        Kt[e * KT_STRIDE + k] = ok ? Kg[off] : 0.f;
        Vs[k * VS_STRIDE + e] = ok ? Vg[off] : 0.f;
    }
    __syncthreads();

    {
        const int tq = tid >> 4;
        const int tk = tid & 15;
        u64 acc2[8][5];
#pragma unroll
        for (int i = 0; i < 8; i++)
#pragma unroll
            for (int j = 0; j < 5; j++) acc2[i][j] = 0ull;

#pragma unroll 4
        for (int e = 0; e < EDIM; e++) {
            const float* qrow = Qt + e * QT_STRIDE + tq * 8;
            const float* krow = Kt + e * KT_STRIDE + tk * 10;
            u64 qb[8];
#pragma unroll
            for (int i = 0; i < 4; i++) {
                float2 qp = *(const float2*)(qrow + 2 * i);
                qb[2 * i]     = bcast2(qp.x);
                qb[2 * i + 1] = bcast2(qp.y);
            }
            u64 k2[5];
#pragma unroll
            for (int j = 0; j < 5; j++)
                k2[j] = *(const u64*)(krow + 2 * j);
#pragma unroll
            for (int i = 0; i < 8; i++)
#pragma unroll
                for (int j = 0; j < 5; j++)
                    FMA2(acc2[i][j], qb[i], k2[j], acc2[i][j]);
        }
        const float scale = 0.17677669529663687f;
#pragma unroll
        for (int i = 0; i < 8; i++)
#pragma unroll
            for (int j = 0; j < 5; j++) {
                float2 u = unpack2(acc2[i][j]);
                *(float2*)&S[(tq * 8 + i) * S_STRIDE + tk * 10 + 2 * j] =
                    make_float2(u.x * scale, u.y * scale);
            }
    }
    __syncthreads();

    {
        const int row  = tid >> 1;
        const int half = tid & 1;
        float* r = S + row * S_STRIDE + half * 72;
        float m = -1e30f;
#pragma unroll 8
        for (int k = 0; k < 72; k++) m = fmaxf(m, r[k]);
        m = fmaxf(m, __shfl_xor_sync(0xFFFFFFFFu, m, 1));
        float s = 0.f;
#pragma unroll 8
        for (int k = 0; k < 72; k++) {
            float ex = __expf(r[k] - m);
            r[k] = ex;
            s += ex;
        }
        s += __shfl_xor_sync(0xFFFFFFFFu, s, 1);
        float inv = 1.f / s;
#pragma unroll 8
        for (int k = 0; k < 72; k++) r[k] *= inv;
    }
    __syncthreads();

    {
        const int tq = tid >> 3;
        const int te = tid & 7;
        u64 acc2[4][2];
#pragma unroll
        for (int i = 0; i < 4; i++) { acc2[i][0] = 0ull; acc2[i][1] = 0ull; }

#pragma unroll 4
        for (int k = 0; k < NKEY; k++) {
            u64 a2[4];
#pragma unroll
            for (int i = 0; i < 4; i++)
                a2[i] = bcast2(S[(tq * 4 + i) * S_STRIDE + k]);
            u64 v0 = *(const u64*)&Vs[k * VS_STRIDE + te * 4];
            u64 v1 = *(const u64*)&Vs[k * VS_STRIDE + te * 4 + 2];
#pragma unroll
            for (int i = 0; i < 4; i++) {
                FMA2(acc2[i][0], a2[i], v0, acc2[i][0]);
                FMA2(acc2[i][1], a2[i], v1, acc2[i][1]);
            }
        }
#pragma unroll
        for (int i = 0; i < 4; i++) {
            int q = tq * 4 + i;
            int r = wi * 8 + (q >> 3);
            int c = wj * 8 + (q & 7);
            float2 u0 = unpack2(acc2[i][0]);
            float2 u1 = unpack2(acc2[i][1]);
            float4 v4 = make_float4(u0.x, u0.y, u1.x, u1.y);
            *(float4*)(g_att + ((size_t)b * PIX + r * WW + c) * CCH
                       + head * EDIM + te * 4) = v4;
        }
    }
}

// ---------------------------------------------------------------------------
// Kernel 3: output projection via mma.sync bf16x3.
// A = g_att (fp32, converted on load), B = W2 hi/lo.
// y[b][n][p0+m] = D[m][n] + b2[n]
// ---------------------------------------------------------------------------
__global__ __launch_bounds__(256) void proj_mma(const float* __restrict__ b2,
                                                float* __restrict__ y) {
    extern __shared__ char smem[];
    char* sAh = smem;
    char* sAl = smem + TILE_B;
    char* sBh = smem + 2 * TILE_B;
    char* sBl = smem + 3 * TILE_B;
    const u32 uAh = smem_u32(sAh), uAl = smem_u32(sAl);
    const u32 uBh = smem_u32(sBh), uBl = smem_u32(sBl);

    const int tid = threadIdx.x;
    const int lane = tid & 31, wid = tid >> 5;
    const int warp_m = wid >> 1, warp_n = wid & 1;
    const int b  = blockIdx.z;
    const int p0 = blockIdx.x * 128;
    const int n0 = blockIdx.y * 128;

    const int g = lane >> 3, rr = lane & 7;
    const u32 offA = (u32)(((warp_m * 32 + rr + (g & 1) * 8) * KPAD + (g >> 1) * 8) * 2);
    const u32 offB = (u32)(((warp_n * 64 + (g >> 1) * 8 + rr) * KPAD + (g & 1) * 8) * 2);

    float acc[2][8][4];
#pragma unroll
    for (int ma = 0; ma < 2; ma++)
#pragma unroll
        for (int na = 0; na < 8; na++)
#pragma unroll
            for (int v = 0; v < 4; v++) acc[ma][na][v] = 0.f;

    const float* ab = g_att + (size_t)b * PIX * CCH;

    for (int c0 = 0; c0 < CCH; c0 += 64) {
        // A: 128 rows x 64 k fp32 -> split to bf16 hi/lo
#pragma unroll
        for (int t = 0; t < 8; t++) {
            int idx = tid + t * 256;           // 0..2047
            int row = idx >> 4, seg = idx & 15;   // 16 float4 per row
            float4 v4 = *(const float4*)(ab + (size_t)(p0 + row) * CCH + c0 + seg * 4);
            __nv_bfloat16 h0 = __float2bfloat16(v4.x);
            __nv_bfloat16 h1 = __float2bfloat16(v4.y);
            __nv_bfloat16 h2 = __float2bfloat16(v4.z);
            __nv_bfloat16 h3 = __float2bfloat16(v4.w);
            __nv_bfloat162 hh01; hh01.x = h0; hh01.y = h1;
            __nv_bfloat162 hh23; hh23.x = h2; hh23.y = h3;
            __nv_bfloat162 ll01;
            ll01.x = __float2bfloat16(v4.x - __bfloat162float(h0));
            ll01.y = __float2bfloat16(v4.y - __bfloat162float(h1));
            __nv_bfloat162 ll23;
            ll23.x = __float2bfloat16(v4.z - __bfloat162float(h2));
            ll23.y = __float2bfloat16(v4.w - __bfloat162float(h3));
            int doff = row * (KPAD * 2) + seg * 8;
            *(__nv_bfloat162*)(sAh + doff)     = hh01;
            *(__nv_bfloat162*)(sAh + doff + 4) = hh23;
            *(__nv_bfloat162*)(sAl + doff)     = ll01;
            *(__nv_bfloat162*)(sAl + doff + 4) = ll23;
        }
        // B: 128 rows x 64 k from W2 hi/lo
#pragma unroll
        for (int t = 0; t < 4; t++) {
            int idx = tid + t * 256;
            int row = idx >> 3, seg = idx & 7;
            size_t src = ((size_t)(n0 + row)) * CCH + c0 + seg * 8;
            int doff = row * (KPAD * 2) + seg * 16;
            *(int4*)(sBh + doff) = *(const int4*)(g_w2h + src);
            *(int4*)(sBl + doff) = *(const int4*)(g_w2l + src);
        }
        __syncthreads();

#pragma unroll
        for (int ks = 0; ks < 4; ks++) {
            const u32 ko = ks * 32;
            u32 ah[2][4], al[2][4];
            ldsm4(ah[0], uAh + offA + ko);
            ldsm4(ah[1], uAh + offA + ko + 16 * KPAD * 2);
            ldsm4(al[0], uAl + offA + ko);
            ldsm4(al[1], uAl + offA + ko + 16 * KPAD * 2);
#pragma unroll
            for (int ng = 0; ng < 4; ng++) {
                u32 bh[4], bl[4];
                ldsm4(bh, uBh + offB + ko + ng * (16 * KPAD * 2));
                ldsm4(bl, uBl + offB + ko + ng * (16 * KPAD * 2));
#pragma unroll
                for (int h = 0; h < 2; h++) {
                    const u32* bhf = bh + 2 * h;
                    const u32* blf = bl + 2 * h;
                    int na = ng * 2 + h;
#pragma unroll
                    for (int ma = 0; ma < 2; ma++) {
                        mma_bf16(acc[ma][na], ah[ma], bhf);
                        mma_bf16(acc[ma][na], ah[ma], blf);
                        mma_bf16(acc[ma][na], al[ma], bhf);
                    }
                }
            }
        }
        __syncthreads();
    }

    // Epilogue: y[b][n][p]
    const int r = lane >> 2;
    const int cp = (lane & 3) * 2;
#pragma unroll
    for (int ma = 0; ma < 2; ma++) {
#pragma unroll
        for (int na = 0; na < 8; na++) {
#pragma unroll
            for (int v = 0; v < 4; v++) {
                int m = p0 + warp_m * 32 + ma * 16 + r + (v >> 1) * 8;
                int n = n0 + warp_n * 64 + na * 8 + cp + (v & 1);
                y[((size_t)(b * CCH + n)) * PIX + m] = acc[ma][na][v] + b2[n];
            }
        }
    }
}

// ---------------------------------------------------------------------------
extern "C" void kernel_launch(void* const* d_in, const int* in_sizes, int n_in,
                              void* d_out, int out_size) {
    const float* x  = (const float*)d_in[0];
    const float* W1 = (const float*)d_in[1];
    const float* b1 = (const float*)d_in[2];
    const float* W2 = (const float*)d_in[3];
    const float* b2 = (const float*)d_in[4];
    float* y = (float*)d_out;

    const int attn_smem = SMEM_FLOATS * (int)sizeof(float);
    cudaFuncSetAttribute(attn_kernel,
                         cudaFuncAttributeMaxDynamicSharedMemorySize, attn_smem);
    cudaFuncSetAttribute(qkv_mma,
                         cudaFuncAttributeMaxDynamicSharedMemorySize, GEMM_SMEM);
    cudaFuncSetAttribute(proj_mma,
                         cudaFuncAttributeMaxDynamicSharedMemorySize, GEMM_SMEM);

    __nv_bfloat16 *w1h, *w1l, *w2h, *w2l;
    cudaGetSymbolAddress((void**)&w1h, g_w1h);
    cudaGetSymbolAddress((void**)&w1l, g_w1l);
    cudaGetSymbolAddress((void**)&w2h, g_w2h);
    cudaGetSymbolAddress((void**)&w2l, g_w2l);

    // 0) fp32 -> bf16 hi/lo splits
    conv_x<<<dim3(PIX / 32, CCH / 32, BATCH), dim3(32, 8)>>>(x);
    conv_w<<<(768 * CCH + 255) / 256, 256>>>(W1, w1h, w1l, 768 * CCH);
    conv_w<<<(CCH * CCH + 255) / 256, 256>>>(W2, w2h, w2l, CCH * CCH);

    // 1) QKV: M=4096 (x128), N=768 (x128), per batch
    qkv_mma<<<dim3(PIX / 128, 768 / 128, BATCH), 256, GEMM_SMEM>>>(b1);

    // 2) Attention
    attn_kernel<<<dim3(NWIN * NWIN, NH, BATCH), 128, attn_smem>>>();

    // 3) Output projection: N=256 (x128)
    proj_mma<<<dim3(PIX / 128, CCH / 128, BATCH), 256, GEMM_SMEM>>>(b2, y);
}

// round 8
// speedup vs baseline: 1.4286x; 1.0949x over previous
#include <cuda_runtime.h>
#include <cuda_bf16.h>
#include <math.h>

#define NH    8
#define EDIM  32
#define WS    8
#define MO    12
#define NKEY  (MO*MO)      // 144
#define NKPAD 160
#define BATCH 16
#define CCH   256
#define HH    64
#define WW    64
#define PIX   (HH*WW)      // 4096
#define NWIN  8

typedef unsigned long long u64;
typedef unsigned int u32;

// Scratch buffers
__device__ float g_Q[BATCH * NH * PIX * EDIM];    // (b, head, pixel, e)
__device__ float g_K[BATCH * NH * PIX * EDIM];
__device__ float g_V[BATCH * NH * PIX * EDIM];

// bf16 hi/lo split scratch
__device__ __nv_bfloat16 g_xh[BATCH * PIX * CCH];   // x transposed: (b, p, c)
__device__ __nv_bfloat16 g_xl[BATCH * PIX * CCH];
__device__ __nv_bfloat16 g_w1h[768 * CCH];          // (n, k)
__device__ __nv_bfloat16 g_w1l[768 * CCH];
__device__ __nv_bfloat16 g_w2h[CCH * CCH];
__device__ __nv_bfloat16 g_w2l[CCH * CCH];
__device__ __nv_bfloat16 g_atth[BATCH * PIX * CCH]; // attn out hi (b, p, c)
__device__ __nv_bfloat16 g_attl[BATCH * PIX * CCH]; // attn out lo

// ---- packed f32x2 helpers ----
__device__ __forceinline__ u64 pack2(float lo, float hi) {
    u64 r; asm("mov.b64 %0, {%1, %2};" : "=l"(r) : "f"(lo), "f"(hi)); return r;
}
__device__ __forceinline__ u64 bcast2(float v) { return pack2(v, v); }
__device__ __forceinline__ float2 unpack2(u64 v) {
    float2 r; asm("mov.b64 {%0, %1}, %2;" : "=f"(r.x), "=f"(r.y) : "l"(v)); return r;
}
#define FMA2(d, a, b, c) \
    asm("fma.rn.f32x2 %0, %1, %2, %3;" : "=l"(d) : "l"(a), "l"(b), "l"(c))

// ---- fast exp on FMA pipe (no MUFU). x <= ~0 expected. ----
__device__ __forceinline__ float fast_exp(float x) {
    float y = fmaxf(x * 1.4426950408889634f, -125.0f);
    float z = y + 12582912.0f;                    // round-to-nearest-int trick
    int   n = __float_as_int(z) - 0x4B400000;
    float f = y - (z - 12582912.0f);              // f in [-0.5, 0.5]
    float p = 1.540353039338161e-4f;
    p = fmaf(p, f, 0.0013333558146428443f);
    p = fmaf(p, f, 0.009618129107628477f);
    p = fmaf(p, f, 0.05550410866482158f);
    p = fmaf(p, f, 0.2402265069591007f);
    p = fmaf(p, f, 0.6931471805599453f);
    p = fmaf(p, f, 1.0f);
    return p * __int_as_float((n + 127) << 23);
}

// ---- mma.sync helpers (baseline PTX) ----
__device__ __forceinline__ u32 smem_u32(const void* p) {
    u32 a; asm("{ .reg .u64 t; cvta.to.shared.u64 t, %1; cvt.u32.u64 %0, t; }"
               : "=r"(a) : "l"(p));
    return a;
}
__device__ __forceinline__ void ldsm4(u32* r, u32 addr) {
    asm volatile("ldmatrix.sync.aligned.m8n8.x4.shared.b16 {%0,%1,%2,%3}, [%4];"
                 : "=r"(r[0]), "=r"(r[1]), "=r"(r[2]), "=r"(r[3]) : "r"(addr));
}
__device__ __forceinline__ void mma_bf16(float* d, const u32* a, const u32* b) {
    asm volatile(
        "mma.sync.aligned.m16n8k16.row.col.f32.bf16.bf16.f32 "
        "{%0,%1,%2,%3}, {%4,%5,%6,%7}, {%8,%9}, {%0,%1,%2,%3};"
        : "+f"(d[0]), "+f"(d[1]), "+f"(d[2]), "+f"(d[3])
        : "r"(a[0]), "r"(a[1]), "r"(a[2]), "r"(a[3]), "r"(b[0]), "r"(b[1]));
}
__device__ __forceinline__ void cp16(u32 dst, const void* src) {
    asm volatile("cp.async.cg.shared.global [%0], [%1], 16;"
                 :: "r"(dst), "l"(src));
}
#define CP_COMMIT() asm volatile("cp.async.commit_group;" ::: "memory")
#define CP_WAIT0()  asm volatile("cp.async.wait_group 0;" ::: "memory")

// GEMM smem: 4 bf16 arrays of 128 rows x 72 (64 used, pad->144B rows)
#define KPAD 72
#define TILE_B (128 * KPAD * 2)       // 18432 bytes
#define GEMM_SMEM (4 * TILE_B)        // 73728 bytes

// ---------------------------------------------------------------------------
// Conversion kernels
// ---------------------------------------------------------------------------
__global__ void conv_x(const float* __restrict__ x) {
    __shared__ float tile[32][33];
    const int b  = blockIdx.z;
    const int p0 = blockIdx.x * 32;
    const int c0 = blockIdx.y * 32;
    const int tx = threadIdx.x, ty = threadIdx.y;   // 32 x 8
    const float* xb = x + ((size_t)b * CCH + c0) * PIX + p0;
#pragma unroll
    for (int i = 0; i < 32; i += 8)
        tile[ty + i][tx] = xb[(size_t)(ty + i) * PIX + tx];
    __syncthreads();
#pragma unroll
    for (int i = 0; i < 32; i += 8) {
        int p = p0 + ty + i;
        float v = tile[tx][ty + i];
        __nv_bfloat16 hi = __float2bfloat16(v);
        __nv_bfloat16 lo = __float2bfloat16(v - __bfloat162float(hi));
        size_t o = ((size_t)b * PIX + p) * CCH + c0 + tx;
        g_xh[o] = hi;
        g_xl[o] = lo;
    }
}

__global__ void conv_w(const float* __restrict__ w, __nv_bfloat16* __restrict__ wh,
                       __nv_bfloat16* __restrict__ wl, int n) {
    int i = blockIdx.x * 256 + threadIdx.x;
    if (i < n) {
        float v = w[i];
        __nv_bfloat16 hi = __float2bfloat16(v);
        __nv_bfloat16 lo = __float2bfloat16(v - __bfloat162float(hi));
        wh[i] = hi;
        wl[i] = lo;
    }
}

// ---------------------------------------------------------------------------
// Kernel 1: QKV projection via mma.sync bf16x3 + cp.async, 2 CTAs/SM.
// ---------------------------------------------------------------------------
__global__ __launch_bounds__(256, 2) void qkv_mma(const float* __restrict__ b1) {
    extern __shared__ char smem[];
    char* sAh = smem;
    char* sAl = smem + TILE_B;
    char* sBh = smem + 2 * TILE_B;
    char* sBl = smem + 3 * TILE_B;
    const u32 uAh = smem_u32(sAh), uAl = smem_u32(sAl);
    const u32 uBh = smem_u32(sBh), uBl = smem_u32(sBl);

    const int tid = threadIdx.x;
    const int lane = tid & 31, wid = tid >> 5;
    const int warp_m = wid >> 1, warp_n = wid & 1;
    const int b  = blockIdx.z;
    const int p0 = blockIdx.x * 128;
    const int n0 = blockIdx.y * 128;

    const int g = lane >> 3, rr = lane & 7;
    const u32 offA = (u32)(((warp_m * 32 + rr + (g & 1) * 8) * KPAD + (g >> 1) * 8) * 2);
    const u32 offB = (u32)(((warp_n * 64 + (g >> 1) * 8 + rr) * KPAD + (g & 1) * 8) * 2);

    float acc[2][8][4];
#pragma unroll
    for (int ma = 0; ma < 2; ma++)
#pragma unroll
        for (int na = 0; na < 8; na++)
#pragma unroll
            for (int v = 0; v < 4; v++) acc[ma][na][v] = 0.f;

    const __nv_bfloat16* Ah = g_xh + (size_t)b * PIX * CCH;
    const __nv_bfloat16* Al = g_xl + (size_t)b * PIX * CCH;

    for (int c0 = 0; c0 < CCH; c0 += 64) {
#pragma unroll
        for (int t = 0; t < 4; t++) {
            int idx = tid + t * 256;          // 0..1023
            int row = idx >> 3, seg = idx & 7;
            size_t srcA = ((size_t)(p0 + row)) * CCH + c0 + seg * 8;
            size_t srcB = ((size_t)(n0 + row)) * CCH + c0 + seg * 8;
            u32 doff = (u32)(row * (KPAD * 2) + seg * 16);
            cp16(uAh + doff, Ah + srcA);
            cp16(uAl + doff, Al + srcA);
            cp16(uBh + doff, g_w1h + srcB);
            cp16(uBl + doff, g_w1l + srcB);
        }
        CP_COMMIT();
        CP_WAIT0();
        __syncthreads();

#pragma unroll
        for (int ks = 0; ks < 4; ks++) {
            const u32 ko = ks * 32;           // 16 k * 2 bytes
            u32 ah[2][4], al[2][4];
            ldsm4(ah[0], uAh + offA + ko);
            ldsm4(ah[1], uAh + offA + ko + 16 * KPAD * 2);
            ldsm4(al[0], uAl + offA + ko);
            ldsm4(al[1], uAl + offA + ko + 16 * KPAD * 2);
#pragma unroll
            for (int ng = 0; ng < 4; ng++) {
                u32 bh[4], bl[4];
                ldsm4(bh, uBh + offB + ko + ng * (16 * KPAD * 2));
                ldsm4(bl, uBl + offB + ko + ng * (16 * KPAD * 2));
#pragma unroll
                for (int h = 0; h < 2; h++) {
                    const u32* bhf = bh + 2 * h;
                    const u32* blf = bl + 2 * h;
                    int na = ng * 2 + h;
#pragma unroll
                    for (int ma = 0; ma < 2; ma++) {
                        mma_bf16(acc[ma][na], ah[ma], bhf);
                        mma_bf16(acc[ma][na], ah[ma], blf);
                        mma_bf16(acc[ma][na], al[ma], bhf);
                    }
                }
            }
        }
        __syncthreads();
    }

    // Epilogue: scatter into Q/K/V
    const int r = lane >> 2;
    const int cp = (lane & 3) * 2;
#pragma unroll
    for (int ma = 0; ma < 2; ma++) {
#pragma unroll
        for (int na = 0; na < 8; na++) {
#pragma unroll
            for (int v = 0; v < 4; v++) {
                int m  = p0 + warp_m * 32 + ma * 16 + r + (v >> 1) * 8;
                int oc = n0 + warp_n * 64 + na * 8 + cp + (v & 1);
                float val = acc[ma][na][v] + b1[oc];
                int type = oc % 3;
                int ch   = oc / 3;
                int head = ch >> 5;
                int e    = ch & 31;
                float* dst = (type == 0) ? g_Q : (type == 1) ? g_K : g_V;
                dst[((size_t)(b * NH + head) * PIX + m) * EDIM + e] = val;
            }
        }
    }
}

// ---------------------------------------------------------------------------
// Kernel 2: windowed attention. fp32 FFMA2 GEMMs + FMA-pipe softmax (no MUFU).
// Epilogue writes bf16 hi/lo for the projection GEMM.
// ---------------------------------------------------------------------------
#define QT_STRIDE 66
#define KT_STRIDE 162
#define VS_STRIDE 34
#define S_STRIDE  162
#define SMEM_FLOATS (EDIM*QT_STRIDE + EDIM*KT_STRIDE + NKEY*VS_STRIDE + 64*S_STRIDE)

__global__ __launch_bounds__(128) void attn_kernel() {
    extern __shared__ float sm[];
    float* Qt = sm;                          // 32 x 66   [e][q]
    float* Kt = Qt + EDIM * QT_STRIDE;       // 32 x 162  [e][k]
    float* Vs = Kt + EDIM * KT_STRIDE;       // 144 x 34  [k][e]
    float* S  = Vs + NKEY * VS_STRIDE;       // 64 x 162

    const int b    = blockIdx.z;
    const int head = blockIdx.y;
    const int wi   = blockIdx.x >> 3;
    const int wj   = blockIdx.x & 7;
    const int tid  = threadIdx.x;

    const size_t hb = (size_t)(b * NH + head) * PIX * EDIM;
    const float* Qg = g_Q + hb;
    const float* Kg = g_K + hb;
    const float* Vg = g_V + hb;

    for (int idx = tid; idx < EDIM * (NKPAD - NKEY); idx += 128) {
        int e = idx >> 4, k = NKEY + (idx & 15);
        Kt[e * KT_STRIDE + k] = 0.f;
    }
    for (int idx = tid; idx < 64 * EDIM; idx += 128) {
        int q = idx >> 5, e = idx & 31;
        int r = wi * 8 + (q >> 3);
        int c = wj * 8 + (q & 7);
        Qt[e * QT_STRIDE + q] = Qg[(size_t)(r * WW + c) * EDIM + e];
    }
    for (int idx = tid; idx < NKEY * EDIM; idx += 128) {
        int k = idx >> 5, e = idx & 31;
        int kr = k / MO, kc = k % MO;
        int r = wi * 8 - 2 + kr;
        int c = wj * 8 - 2 + kc;
        bool ok = (r >= 0) && (r < HH) && (c >= 0) && (c < WW);
        size_t off = (size_t)(r * WW + c) * EDIM + e;
        Kt[e * KT_STRIDE + k] = ok ? Kg[off] : 0.f;
        Vs[k * VS_STRIDE + e] = ok ? Vg[off] : 0.f;
    }
    __syncthreads();

    {
        const int tq = tid >> 4;
        const int tk = tid & 15;
        u64 acc2[8][5];
#pragma unroll
        for (int i = 0; i < 8; i++)
#pragma unroll
            for (int j = 0; j < 5; j++) acc2[i][j] = 0ull;

#pragma unroll 4
        for (int e = 0; e < EDIM; e++) {
            const float* qrow = Qt + e * QT_STRIDE + tq * 8;
            const float* krow = Kt + e * KT_STRIDE + tk * 10;
            u64 qb[8];
#pragma unroll
            for (int i = 0; i < 4; i++) {
                float2 qp = *(const float2*)(qrow + 2 * i);
                qb[2 * i]     = bcast2(qp.x);
                qb[2 * i + 1] = bcast2(qp.y);
            }
            u64 k2[5];
#pragma unroll
            for (int j = 0; j < 5; j++)
                k2[j] = *(const u64*)(krow + 2 * j);
#pragma unroll
            for (int i = 0; i < 8; i++)
#pragma unroll
                for (int j = 0; j < 5; j++)
                    FMA2(acc2[i][j], qb[i], k2[j], acc2[i][j]);
        }
        const float scale = 0.17677669529663687f;
#pragma unroll
        for (int i = 0; i < 8; i++)
#pragma unroll
            for (int j = 0; j < 5; j++) {
                float2 u = unpack2(acc2[i][j]);
                *(float2*)&S[(tq * 8 + i) * S_STRIDE + tk * 10 + 2 * j] =
                    make_float2(u.x * scale, u.y * scale);
            }
    }
    __syncthreads();

    // Softmax over first 144 cols: 2 threads per row, FMA-pipe exp
    {
        const int row  = tid >> 1;
        const int half = tid & 1;
        float* r = S + row * S_STRIDE + half * 72;
        float m = -1e30f;
#pragma unroll 8
        for (int k = 0; k < 72; k++) m = fmaxf(m, r[k]);
        m = fmaxf(m, __shfl_xor_sync(0xFFFFFFFFu, m, 1));
        float s = 0.f;
#pragma unroll 8
        for (int k = 0; k < 72; k++) {
            float ex = fast_exp(r[k] - m);
            r[k] = ex;
            s += ex;
        }
        s += __shfl_xor_sync(0xFFFFFFFFu, s, 1);
        float inv = 1.f / s;
#pragma unroll 8
        for (int k = 0; k < 72; k++) r[k] *= inv;
    }
    __syncthreads();

    // out = A @ V, write bf16 hi/lo to g_atth/g_attl
    {
        const int tq = tid >> 3;
        const int te = tid & 7;
        u64 acc2[4][2];
#pragma unroll
        for (int i = 0; i < 4; i++) { acc2[i][0] = 0ull; acc2[i][1] = 0ull; }

#pragma unroll 4
        for (int k = 0; k < NKEY; k++) {
            u64 a2[4];
#pragma unroll
            for (int i = 0; i < 4; i++)
                a2[i] = bcast2(S[(tq * 4 + i) * S_STRIDE + k]);
            u64 v0 = *(const u64*)&Vs[k * VS_STRIDE + te * 4];
            u64 v1 = *(const u64*)&Vs[k * VS_STRIDE + te * 4 + 2];
#pragma unroll
            for (int i = 0; i < 4; i++) {
                FMA2(acc2[i][0], a2[i], v0, acc2[i][0]);
                FMA2(acc2[i][1], a2[i], v1, acc2[i][1]);
            }
        }
#pragma unroll
        for (int i = 0; i < 4; i++) {
            int q = tq * 4 + i;
            int r = wi * 8 + (q >> 3);
            int c = wj * 8 + (q & 7);
            float2 u0 = unpack2(acc2[i][0]);
            float2 u1 = unpack2(acc2[i][1]);
            float o[4] = { u0.x, u0.y, u1.x, u1.y };
            __nv_bfloat16 hi[4], lo[4];
#pragma unroll
            for (int v = 0; v < 4; v++) {
                hi[v] = __float2bfloat16(o[v]);
                lo[v] = __float2bfloat16(o[v] - __bfloat162float(hi[v]));
            }
            size_t base = ((size_t)b * PIX + r * WW + c) * CCH + head * EDIM + te * 4;
            *(u64*)(g_atth + base) = *(const u64*)hi;
            *(u64*)(g_attl + base) = *(const u64*)lo;
        }
    }
}

// ---------------------------------------------------------------------------
// Kernel 3: output projection via mma.sync bf16x3 + cp.async, 2 CTAs/SM.
// ---------------------------------------------------------------------------
__global__ __launch_bounds__(256, 2) void proj_mma(const float* __restrict__ b2,
                                                   float* __restrict__ y) {
    extern __shared__ char smem[];
    char* sAh = smem;
    char* sAl = smem + TILE_B;
    char* sBh = smem + 2 * TILE_B;
    char* sBl = smem + 3 * TILE_B;
    const u32 uAh = smem_u32(sAh), uAl = smem_u32(sAl);
    const u32 uBh = smem_u32(sBh), uBl = smem_u32(sBl);

    const int tid = threadIdx.x;
    const int lane = tid & 31, wid = tid >> 5;
    const int warp_m = wid >> 1, warp_n = wid & 1;
    const int b  = blockIdx.z;
    const int p0 = blockIdx.x * 128;
    const int n0 = blockIdx.y * 128;

    const int g = lane >> 3, rr = lane & 7;
    const u32 offA = (u32)(((warp_m * 32 + rr + (g & 1) * 8) * KPAD + (g >> 1) * 8) * 2);
    const u32 offB = (u32)(((warp_n * 64 + (g >> 1) * 8 + rr) * KPAD + (g & 1) * 8) * 2);

    float acc[2][8][4];
#pragma unroll
    for (int ma = 0; ma < 2; ma++)
#pragma unroll
        for (int na = 0; na < 8; na++)
#pragma unroll
            for (int v = 0; v < 4; v++) acc[ma][na][v] = 0.f;

    const __nv_bfloat16* Ah = g_atth + (size_t)b * PIX * CCH;
    const __nv_bfloat16* Al = g_attl + (size_t)b * PIX * CCH;

    for (int c0 = 0; c0 < CCH; c0 += 64) {
#pragma unroll
        for (int t = 0; t < 4; t++) {
            int idx = tid + t * 256;
            int row = idx >> 3, seg = idx & 7;
            size_t srcA = ((size_t)(p0 + row)) * CCH + c0 + seg * 8;
            size_t srcB = ((size_t)(n0 + row)) * CCH + c0 + seg * 8;
            u32 doff = (u32)(row * (KPAD * 2) + seg * 16);
            cp16(uAh + doff, Ah + srcA);
            cp16(uAl + doff, Al + srcA);
            cp16(uBh + doff, g_w2h + srcB);
            cp16(uBl + doff, g_w2l + srcB);
        }
        CP_COMMIT();
        CP_WAIT0();
        __syncthreads();

#pragma unroll
        for (int ks = 0; ks < 4; ks++) {
            const u32 ko = ks * 32;
            u32 ah[2][4], al[2][4];
            ldsm4(ah[0], uAh + offA + ko);
            ldsm4(ah[1], uAh + offA + ko + 16 * KPAD * 2);
            ldsm4(al[0], uAl + offA + ko);
            ldsm4(al[1], uAl + offA + ko + 16 * KPAD * 2);
#pragma unroll
            for (int ng = 0; ng < 4; ng++) {
                u32 bh[4], bl[4];
                ldsm4(bh, uBh + offB + ko + ng * (16 * KPAD * 2));
                ldsm4(bl, uBl + offB + ko + ng * (16 * KPAD * 2));
#pragma unroll
                for (int h = 0; h < 2; h++) {
                    const u32* bhf = bh + 2 * h;
                    const u32* blf = bl + 2 * h;
                    int na = ng * 2 + h;
#pragma unroll
                    for (int ma = 0; ma < 2; ma++) {
                        mma_bf16(acc[ma][na], ah[ma], bhf);
                        mma_bf16(acc[ma][na], ah[ma], blf);
                        mma_bf16(acc[ma][na], al[ma], bhf);
                    }
                }
            }
        }
        __syncthreads();
    }

    // Epilogue: y[b][n][p]
    const int r = lane >> 2;
    const int cp = (lane & 3) * 2;
#pragma unroll
    for (int ma = 0; ma < 2; ma++) {
#pragma unroll
        for (int na = 0; na < 8; na++) {
#pragma unroll
            for (int v = 0; v < 4; v++) {
                int m = p0 + warp_m * 32 + ma * 16 + r + (v >> 1) * 8;
                int n = n0 + warp_n * 64 + na * 8 + cp + (v & 1);
                y[((size_t)(b * CCH + n)) * PIX + m] = acc[ma][na][v] + b2[n];
            }
        }
    }
}

// ---------------------------------------------------------------------------
extern "C" void kernel_launch(void* const* d_in, const int* in_sizes, int n_in,
                              void* d_out, int out_size) {
    const float* x  = (const float*)d_in[0];
    const float* W1 = (const float*)d_in[1];
    const float* b1 = (const float*)d_in[2];
    const float* W2 = (const float*)d_in[3];
    const float* b2 = (const float*)d_in[4];
    float* y = (float*)d_out;

    const int attn_smem = SMEM_FLOATS * (int)sizeof(float);
    cudaFuncSetAttribute(attn_kernel,
                         cudaFuncAttributeMaxDynamicSharedMemorySize, attn_smem);
    cudaFuncSetAttribute(qkv_mma,
                         cudaFuncAttributeMaxDynamicSharedMemorySize, GEMM_SMEM);
    cudaFuncSetAttribute(proj_mma,
                         cudaFuncAttributeMaxDynamicSharedMemorySize, GEMM_SMEM);

    __nv_bfloat16 *w1h, *w1l, *w2h, *w2l;
    cudaGetSymbolAddress((void**)&w1h, g_w1h);
    cudaGetSymbolAddress((void**)&w1l, g_w1l);
    cudaGetSymbolAddress((void**)&w2h, g_w2h);
    cudaGetSymbolAddress((void**)&w2l, g_w2l);

    // 0) fp32 -> bf16 hi/lo splits
    conv_x<<<dim3(PIX / 32, CCH / 32, BATCH), dim3(32, 8)>>>(x);
    conv_w<<<(768 * CCH + 255) / 256, 256>>>(W1, w1h, w1l, 768 * CCH);
    conv_w<<<(CCH * CCH + 255) / 256, 256>>>(W2, w2h, w2l, CCH * CCH);

    // 1) QKV: M=4096 (x128), N=768 (x128), per batch
    qkv_mma<<<dim3(PIX / 128, 768 / 128, BATCH), 256, GEMM_SMEM>>>(b1);

    // 2) Attention
    attn_kernel<<<dim3(NWIN * NWIN, NH, BATCH), 128, attn_smem>>>();

    // 3) Output projection: N=256 (x128)
    proj_mma<<<dim3(PIX / 128, CCH / 128, BATCH), 256, GEMM_SMEM>>>(b2, y);
}